// round 5
// baseline (speedup 1.0000x reference)
#include <cuda_runtime.h>

// IDGNN restructured (math validated in R2/R4, rel_err ~2e-7):
//   p_i = MLP_{0,i}(x);  u = x + A*p0;  d = p1 - p0
//   Un_i = u*W1e[1,i]; Dt_i = d*W1e[1,i]   (W1e[k] = w1[k]+w1[k+128])
//   S_t = sum_{n in N(t)} relu(Un0[n] + Dt0[t] + b1[1,0])
//   out[t] = u_t + self_t*d_t + S_t*w2[1,0] + deg_t*b2[1,0]
//            + self_t*( (relu(Un1_t+Dt1_t+b1[1,1])*w2[1,1]+b2[1,1])
//                      -(relu(Un0_t+Dt0_t+b1[1,0])*w2[1,0]+b2[1,0]) )
// R5: single fused kernel, 128 co-resident blocks, software grid barriers.
// Neighbor lists built once (P2) and reused in P3 via persistent shared mem.
// g_adj restored to zero in P3 so every graph replay sees clean state.

#define NN 256
#define DD 128
#define NB 128   // grid size; must be <= #SMs for the barrier to be safe

// ---- device scratch (zero-init at load; g_adj re-zeroed each call in P3) ----
__device__ unsigned g_adj[NN * 8];
__device__ __align__(16) float g_W1e[4 * DD * DD];
__device__ __align__(16) float g_p0[NN * DD];
__device__ __align__(16) float g_p1[NN * DD];
__device__ __align__(16) float g_u [NN * DD];
__device__ __align__(16) float g_d [NN * DD];
__device__ __align__(16) float g_UD[4][NN * DD];   // 0:Un0 1:Dt0 2:Un1 3:Dt1
__device__ unsigned g_bar_count;
__device__ unsigned g_bar_gen;

__device__ __forceinline__ float4 f4add(float4 a, float4 b) {
    return make_float4(a.x + b.x, a.y + b.y, a.z + b.z, a.w + b.w);
}
__device__ __forceinline__ float4 f4fma(float s, float4 w, float4 a) {
    return make_float4(fmaf(s, w.x, a.x), fmaf(s, w.y, a.y),
                       fmaf(s, w.z, a.z), fmaf(s, w.w, a.w));
}
__device__ __forceinline__ float4 f4relu(float4 a) {
    return make_float4(fmaxf(a.x, 0.f), fmaxf(a.y, 0.f),
                       fmaxf(a.z, 0.f), fmaxf(a.w, 0.f));
}

// Grid-wide barrier. All NB blocks co-resident (NB <= SM count, 1 blk/SM).
__device__ __forceinline__ void grid_sync() {
    __syncthreads();
    if (threadIdx.x == 0) {
        __threadfence();
        unsigned gen = atomicAdd(&g_bar_gen, 0u);
        unsigned arrived = atomicAdd(&g_bar_count, 1u);
        if (arrived == NB - 1) {
            atomicExch(&g_bar_count, 0u);
            __threadfence();
            atomicAdd(&g_bar_gen, 1u);       // release
        } else {
            while (atomicAdd(&g_bar_gen, 0u) == gen) __nanosleep(64);
        }
    }
    __syncthreads();
}

// Expand g_adj[row] bitmask into nbr[] (full warp). Returns count.
__device__ __forceinline__ int build_list(int row, int* nbr) {
    int lane = threadIdx.x & 31;
    unsigned word = (lane < 8) ? g_adj[row * 8 + lane] : 0u;
    int pc = __popc(word);
    int inc = pc;
#pragma unroll
    for (int off = 1; off < 8; off <<= 1) {
        int v = __shfl_up_sync(0xffffffffu, inc, off);
        if (lane >= off) inc += v;
    }
    int base = inc - pc;
    if (lane < 8) {
        unsigned bits = word; int o = base;
        while (bits) { int b = __ffs(bits) - 1; bits &= bits - 1; nbr[o++] = lane * 32 + b; }
    }
    return __shfl_sync(0xffffffffu, inc, 7);
}

struct Smem {
    int nbr[4][NN];     // persists P2 -> P3 (blocks < 64 own the same rows)
    int cnts[4];
    int selfS[4];
    union {
        struct { float S[4][DD];  float red[4][4][DD]; } p1;                  // 10 KB
        struct { float U[4][DD];  float D[4][DD]; float red[4][8][DD]; } p2;  // 20 KB
        struct { float Ssum[4][DD]; float red[4][4][DD]; float Hs[2][DD]; } p3; // 11 KB
    } u;
};

__global__ void __launch_bounds__(128, 1)
k_fused(const int* __restrict__ ei32, int E,
        const float4* __restrict__ x4, const float4* __restrict__ w14,
        const float* __restrict__ b1, const float4* __restrict__ w24,
        const float* __restrict__ b2, float* __restrict__ out) {
    __shared__ Smem sm;
    int tid = threadIdx.x, lane = tid & 31, w = tid >> 5, bid = blockIdx.x;

    // ================= P0: edge scatter + W1e = w1[:128]+w1[128:] ==========
    {
        // dtype sniff: int64 node ids (<256, nonneg) => odd int32 words zero
        int probe = (2 * tid + 1 < 2 * E) ? ei32[2 * tid + 1] : 0;
        int is64 = __syncthreads_and(probe == 0);
        for (int e = bid * 128 + tid; e < E; e += NB * 128) {
            int a, b;
            if (is64) { a = ei32[2 * e]; b = ei32[2 * (E + e)]; }
            else      { a = ei32[e];     b = ei32[E + e]; }
            a &= 255; b &= 255;
            atomicOr(&g_adj[a * 8 + (b >> 5)], 1u << (b & 31));
            atomicOr(&g_adj[b * 8 + (a >> 5)], 1u << (a & 31));
        }
        int j  = bid * 128 + tid;            // float4 index in [0,16384)
        int li = j >> 12, rem = j & 4095;
        ((float4*)g_W1e)[j] = f4add(w14[li * 8192 + rem],
                                    w14[li * 8192 + rem + 4096]);
    }
    grid_sync();

    // ================= P1: p_i = MLP_{0,i}(x), 4 rows/block =================
    {
        int i = bid >> 6, row0 = (bid & 63) * 4;
        ((float4*)sm.u.p1.S[w])[lane] = x4[(row0 + w) * 32 + lane];
        __syncthreads();
        const float4* W = (const float4*)g_W1e + i * 4096;    // W1e[0,i]
        float4 acc[4] = {};
#pragma unroll
        for (int kk = 0; kk < 32; kk++) {
            int k = w * 32 + kk;
            float4 wv = W[k * 32 + lane];
#pragma unroll
            for (int r = 0; r < 4; r++) acc[r] = f4fma(sm.u.p1.S[r][k], wv, acc[r]);
        }
#pragma unroll
        for (int r = 0; r < 4; r++) ((float4*)sm.u.p1.red[w][r])[lane] = acc[r];
        __syncthreads();
        {
            float b1v = b1[i * DD + tid];
            float h[4];
#pragma unroll
            for (int r = 0; r < 4; r++)
                h[r] = sm.u.p1.red[0][r][tid] + sm.u.p1.red[1][r][tid]
                     + sm.u.p1.red[2][r][tid] + sm.u.p1.red[3][r][tid] + b1v;
            __syncthreads();
#pragma unroll
            for (int r = 0; r < 4; r++) sm.u.p1.S[r][tid] = fmaxf(h[r], 0.f);
        }
        __syncthreads();
        const float4* W2 = w24 + i * 4096;                     // w2[0,i]
        float4 a2[4] = {};
#pragma unroll
        for (int kk = 0; kk < 32; kk++) {
            int k = w * 32 + kk;
            float4 wv = W2[k * 32 + lane];
#pragma unroll
            for (int r = 0; r < 4; r++) a2[r] = f4fma(sm.u.p1.S[r][k], wv, a2[r]);
        }
#pragma unroll
        for (int r = 0; r < 4; r++) ((float4*)sm.u.p1.red[w][r])[lane] = a2[r];
        __syncthreads();
        float b2v = b2[i * DD + tid];
        float* dst = i ? g_p1 : g_p0;
#pragma unroll
        for (int r = 0; r < 4; r++)
            dst[(row0 + r) * DD + tid] =
                sm.u.p1.red[0][r][tid] + sm.u.p1.red[1][r][tid]
              + sm.u.p1.red[2][r][tid] + sm.u.p1.red[3][r][tid] + b2v;
    }
    grid_sync();

    // ====== P2: u = x + gather(p0), d = p1-p0; Un_i/Dt_i = {u,d}*W1e[1,i] ===
    {
        int i = bid >> 6, row0 = (bid & 63) * 4;
        int row = row0 + w;
        int cn = build_list(row, sm.nbr[w]);
        if (lane == 0) {
            sm.cnts[w]  = cn;
            sm.selfS[w] = (g_adj[row * 8 + (row >> 5)] >> (row & 31)) & 1;
        }
        const float4* p04 = (const float4*)g_p0;
        float4 a0 = x4[row * 32 + lane];
        float4 a1 = {}, a2 = {}, a3 = {};
        int j = 0;
        for (; j + 4 <= cn; j += 4) {
            a0 = f4add(a0, p04[sm.nbr[w][j]     * 32 + lane]);
            a1 = f4add(a1, p04[sm.nbr[w][j + 1] * 32 + lane]);
            a2 = f4add(a2, p04[sm.nbr[w][j + 2] * 32 + lane]);
            a3 = f4add(a3, p04[sm.nbr[w][j + 3] * 32 + lane]);
        }
        for (; j < cn; j++) a0 = f4add(a0, p04[sm.nbr[w][j] * 32 + lane]);
        float4 uv = f4add(f4add(a0, a1), f4add(a2, a3));
        ((float4*)sm.u.p2.U[w])[lane] = uv;
        float4 p1v = ((const float4*)g_p1)[row * 32 + lane];
        float4 p0v = p04[row * 32 + lane];
        float4 dv = make_float4(p1v.x - p0v.x, p1v.y - p0v.y,
                                p1v.z - p0v.z, p1v.w - p0v.w);
        ((float4*)sm.u.p2.D[w])[lane] = dv;
        if (i == 0) {
            ((float4*)g_u)[row * 32 + lane] = uv;
            ((float4*)g_d)[row * 32 + lane] = dv;
        }
        __syncthreads();
        const float4* W = (const float4*)g_W1e + (2 + i) * 4096;   // W1e[1,i]
        float4 aU[4] = {}, aD[4] = {};
#pragma unroll
        for (int kk = 0; kk < 32; kk++) {
            int k = w * 32 + kk;
            float4 wv = W[k * 32 + lane];
#pragma unroll
            for (int r = 0; r < 4; r++) {
                aU[r] = f4fma(sm.u.p2.U[r][k], wv, aU[r]);
                aD[r] = f4fma(sm.u.p2.D[r][k], wv, aD[r]);
            }
        }
#pragma unroll
        for (int r = 0; r < 4; r++) {
            ((float4*)sm.u.p2.red[w][r])[lane]     = aU[r];
            ((float4*)sm.u.p2.red[w][4 + r])[lane] = aD[r];
        }
        __syncthreads();
#pragma unroll
        for (int v = 0; v < 8; v++) {
            float s = sm.u.p2.red[0][v][tid] + sm.u.p2.red[1][v][tid]
                    + sm.u.p2.red[2][v][tid] + sm.u.p2.red[3][v][tid];
            int r = v & 3, isD = v >> 2;
            g_UD[2 * i + isD][(row0 + r) * DD + tid] = s;
        }
    }
    grid_sync();

    // ===== P3: S_t relu-gather + final matvec + self fix + out (blks<64) ===
    if (bid < 64) {
        int t0 = bid * 4;
        int t  = t0 + w;
        int cn = sm.cnts[w];                 // lists persist from P2 (i==0)
        const float4* UD0 = (const float4*)g_UD[0];
        float4 pre = f4add(((const float4*)g_UD[1])[t * 32 + lane],
                           ((const float4*)(b1 + 2 * DD))[lane]);
        float4 s0 = {}, s1 = {}, s2 = {}, s3 = {};
        int j = 0;
        for (; j + 4 <= cn; j += 4) {
            s0 = f4add(s0, f4relu(f4add(UD0[sm.nbr[w][j]     * 32 + lane], pre)));
            s1 = f4add(s1, f4relu(f4add(UD0[sm.nbr[w][j + 1] * 32 + lane], pre)));
            s2 = f4add(s2, f4relu(f4add(UD0[sm.nbr[w][j + 2] * 32 + lane], pre)));
            s3 = f4add(s3, f4relu(f4add(UD0[sm.nbr[w][j + 3] * 32 + lane], pre)));
        }
        for (; j < cn; j++)
            s0 = f4add(s0, f4relu(f4add(UD0[sm.nbr[w][j] * 32 + lane], pre)));
        ((float4*)sm.u.p3.Ssum[w])[lane] = f4add(f4add(s0, s1), f4add(s2, s3));
        __syncthreads();

        const float4* W20 = w24 + 8192;       // w2[1,0]
        float4 acc[4] = {};
#pragma unroll
        for (int kk = 0; kk < 32; kk++) {
            int k = w * 32 + kk;
            float4 wv = W20[k * 32 + lane];
#pragma unroll
            for (int r = 0; r < 4; r++) acc[r] = f4fma(sm.u.p3.Ssum[r][k], wv, acc[r]);
        }
#pragma unroll
        for (int r = 0; r < 4; r++) ((float4*)sm.u.p3.red[w][r])[lane] = acc[r];
        __syncthreads();

        float b20 = b2[2 * DD + tid];
        float b10 = b1[2 * DD + tid];
#pragma unroll
        for (int r = 0; r < 4; r++) {
            int tt = t0 + r;
            float a2 = sm.u.p3.red[0][r][tid] + sm.u.p3.red[1][r][tid]
                     + sm.u.p3.red[2][r][tid] + sm.u.p3.red[3][r][tid];
            float sf = (float)sm.selfS[r];
            float res = g_u[tt * DD + tid] + sf * g_d[tt * DD + tid]
                      + a2 + (float)sm.cnts[r] * b20;
            if (sm.selfS[r]) {               // block-uniform, rare (~8/256)
                sm.u.p3.Hs[0][tid] = fmaxf(g_UD[0][tt * DD + tid]
                                          + g_UD[1][tt * DD + tid] + b10, 0.f);
                sm.u.p3.Hs[1][tid] = fmaxf(g_UD[2][tt * DD + tid]
                                          + g_UD[3][tt * DD + tid] + b1[3 * DD + tid], 0.f);
                __syncthreads();
                const float* W20f = (const float*)w24 + 32768;
                const float* W21f = (const float*)w24 + 49152;
                float d0 = 0.f, d1 = 0.f;
#pragma unroll 4
                for (int k = 0; k < DD; k++) {
                    d0 = fmaf(sm.u.p3.Hs[0][k], W20f[k * DD + tid], d0);
                    d1 = fmaf(sm.u.p3.Hs[1][k], W21f[k * DD + tid], d1);
                }
                res += (d1 + b2[3 * DD + tid]) - (d0 + b20);
                __syncthreads();
            }
            out[tt * DD + tid] = res;
        }
        // restore adjacency rows t0..t0+3 to zero for the next graph replay
        __syncthreads();
        if (tid < 32) g_adj[t0 * 8 + tid] = 0u;
    }
}

extern "C" void kernel_launch(void* const* d_in, const int* in_sizes, int n_in,
                              void* d_out, int out_size) {
    const float* x  = (const float*)d_in[0];
    const float* w1 = (const float*)d_in[1];
    const float* b1 = (const float*)d_in[2];
    const float* w2 = (const float*)d_in[3];
    const float* b2 = (const float*)d_in[4];
    const int*   ei = (const int*)d_in[5];   // dtype sniffed on device
    int E = in_sizes[5] / 2;
    float* out = (float*)d_out;

    k_fused<<<NB, 128>>>(ei, E, (const float4*)x, (const float4*)w1,
                         b1, (const float4*)w2, b2, out);
}